// round 16
// baseline (speedup 1.0000x reference)
#include <cuda_runtime.h>
#include <cuda_fp16.h>
#include <math.h>
#include <cstdint>

#define D      1024
#define D3     3072
#define D4     4096
#define TSEQ   2048
#define NBATCH 2
#define NTOK   4096
#define NH     16
#define HD     64
#define EPS    1.1920929e-07f

// ---------------------------------------------------------------------------
// Scratch (device globals; no allocations allowed)
// ---------------------------------------------------------------------------
__device__ __half g_a[NTOK * D];        // activations fp16 (GEMM A side)
__device__ __half g_act[NTOK * D4];     // fc1 output fp16
__device__ __half g_qkv[NTOK * D3];     // qkv contiguous fp16 [t, 3d]
// transposed weights fp16 [N,K]
__device__ __half g_wA[D * D3];
__device__ __half g_wP[D * D];
__device__ __half g_wF1[D * D4];
__device__ __half g_wF2[D4 * D];

// ---------------------------------------------------------------------------
// Helpers
// ---------------------------------------------------------------------------
__device__ __forceinline__ uint32_t smem_to_u32(const void* p) {
    uint32_t a;
    asm("{ .reg .u64 t; cvta.to.shared.u64 t, %1; cvt.u32.u64 %0, t; }" : "=r"(a) : "l"(p));
    return a;
}

#define SWZ(off) ((uint32_t)(off) ^ ((((uint32_t)(off) >> 7) & 7) << 4))

__device__ __forceinline__ void ldsm_x4(uint32_t* r, uint32_t addr) {
    asm volatile("ldmatrix.sync.aligned.m8n8.x4.shared.b16 {%0,%1,%2,%3}, [%4];"
                 : "=r"(r[0]), "=r"(r[1]), "=r"(r[2]), "=r"(r[3]) : "r"(addr));
}
__device__ __forceinline__ void ldsm_x2(uint32_t* r, uint32_t addr) {
    asm volatile("ldmatrix.sync.aligned.m8n8.x2.shared.b16 {%0,%1}, [%2];"
                 : "=r"(r[0]), "=r"(r[1]) : "r"(addr));
}
__device__ __forceinline__ void ldsm_x2_trans(uint32_t* r, uint32_t addr) {
    asm volatile("ldmatrix.sync.aligned.m8n8.x2.trans.shared.b16 {%0,%1}, [%2];"
                 : "=r"(r[0]), "=r"(r[1]) : "r"(addr));
}
__device__ __forceinline__ void mma_f16_g(float* d, const uint32_t* a, const uint32_t* b) {
    asm volatile(
        "mma.sync.aligned.m16n8k16.row.col.f32.f16.f16.f32 "
        "{%0,%1,%2,%3}, {%4,%5,%6,%7}, {%8,%9}, {%0,%1,%2,%3};"
        : "+f"(d[0]), "+f"(d[1]), "+f"(d[2]), "+f"(d[3])
        : "r"(a[0]), "r"(a[1]), "r"(a[2]), "r"(a[3]), "r"(b[0]), "r"(b[1]));
}
__device__ __forceinline__ uint32_t pack_f16x2(float a, float b) {
    uint32_t r;
    asm("cvt.rn.f16x2.f32 %0, %1, %2;" : "=r"(r) : "f"(b), "f"(a));
    return r;
}

// ---------------------------------------------------------------------------
// Transpose helper (fp32 -> fp16, [K,N] -> [N,K])
// ---------------------------------------------------------------------------
__device__ __forceinline__ void do_transpose(const float* __restrict__ W, int K, int N,
                                             __half* __restrict__ T,
                                             int tile, float* tbuf /* [32][33] */) {
    int tiles_n = N >> 5;
    int k0 = (tile / tiles_n) << 5;
    int n0 = (tile % tiles_n) << 5;
    int x = threadIdx.x & 31, y = threadIdx.x >> 5;
    #pragma unroll
    for (int i = y; i < 32; i += 8)
        tbuf[i * 33 + x] = W[(size_t)(k0 + i) * N + n0 + x];
    __syncthreads();
    #pragma unroll
    for (int b = y; b < 32; b += 8)
        T[(size_t)(n0 + b) * K + k0 + x] = __float2half_rn(tbuf[x * 33 + b]);
}

// prep_main: rmsnorm1 (4096 blocks) + wA transpose (3072 tiles)
__global__ void prep_main_kernel(const float* __restrict__ x, const float* __restrict__ g1,
                                 __half* __restrict__ oa,
                                 const float* __restrict__ wA, __half* tA) {
    __shared__ float tbuf[32 * 33];
    int bid = blockIdx.x;
    if (bid < NTOK) {
        int row = bid;
        const float4* xr = reinterpret_cast<const float4*>(x + (size_t)row * D);
        float4 v = xr[threadIdx.x];
        float s = v.x * v.x + v.y * v.y + v.z * v.z + v.w * v.w;
        #pragma unroll
        for (int o = 16; o > 0; o >>= 1) s += __shfl_xor_sync(0xffffffffu, s, o);
        __shared__ float ws[8];
        if ((threadIdx.x & 31) == 0) ws[threadIdx.x >> 5] = s;
        __syncthreads();
        float tot = ws[0] + ws[1] + ws[2] + ws[3] + ws[4] + ws[5] + ws[6] + ws[7];
        float inv = rsqrtf(tot * (1.0f / (float)D) + EPS);
        float4 gv = reinterpret_cast<const float4*>(g1)[threadIdx.x];
        size_t off = (size_t)row * D + threadIdx.x * 4;
        *reinterpret_cast<__half2*>(&oa[off])     = __floats2half2_rn(v.x * inv * gv.x, v.y * inv * gv.y);
        *reinterpret_cast<__half2*>(&oa[off + 2]) = __floats2half2_rn(v.z * inv * gv.z, v.w * inv * gv.w);
    } else {
        do_transpose(wA, D, D3, tA, bid - NTOK, tbuf);
    }
}

// prep_w: wP (1024) + wF1 (4096) + wF2 (4096) transposes, side stream
__global__ void prep_w_kernel(const float* __restrict__ wP, const float* __restrict__ wF1,
                              const float* __restrict__ wF2,
                              __half* tP, __half* tF1, __half* tF2) {
    __shared__ float tbuf[32 * 33];
    int bid = blockIdx.x;
    if (bid < 1024) {
        do_transpose(wP, D, D, tP, bid, tbuf);
    } else if (bid < 1024 + 4096) {
        do_transpose(wF1, D, D4, tF1, bid - 1024, tbuf);
    } else {
        do_transpose(wF2, D4, D, tF2, bid - 1024 - 4096, tbuf);
    }
}

// ---------------------------------------------------------------------------
// rmsnorm (standalone, for norm2) -> fp16
// ---------------------------------------------------------------------------
__global__ void rmsnorm_h_kernel(const float* __restrict__ x,
                                 const float* __restrict__ g,
                                 __half* __restrict__ oa) {
    int row = blockIdx.x;
    const float4* xr = reinterpret_cast<const float4*>(x + (size_t)row * D);
    float4 v = xr[threadIdx.x];
    float s = v.x * v.x + v.y * v.y + v.z * v.z + v.w * v.w;
    #pragma unroll
    for (int o = 16; o > 0; o >>= 1) s += __shfl_xor_sync(0xffffffffu, s, o);
    __shared__ float ws[8];
    if ((threadIdx.x & 31) == 0) ws[threadIdx.x >> 5] = s;
    __syncthreads();
    float tot = ws[0] + ws[1] + ws[2] + ws[3] + ws[4] + ws[5] + ws[6] + ws[7];
    float inv = rsqrtf(tot * (1.0f / (float)D) + EPS);
    float4 gv = reinterpret_cast<const float4*>(g)[threadIdx.x];
    size_t off = (size_t)row * D + threadIdx.x * 4;
    *reinterpret_cast<__half2*>(&oa[off])     = __floats2half2_rn(v.x * inv * gv.x, v.y * inv * gv.y);
    *reinterpret_cast<__half2*>(&oa[off + 2]) = __floats2half2_rn(v.z * inv * gv.z, v.w * inv * gv.w);
}

// ---------------------------------------------------------------------------
// Single-fp16 1-pass GEMM (unchanged from R15 451us baseline).
// 128x128, BK=64, 3-stage single-barrier pipeline, 2 CTAs/SM.
// ---------------------------------------------------------------------------
#define EPI_HBIAS 0
#define EPI_GELU  1
#define EPI_RES   2

#define STAGE_BYTES 32768
#define TCG_SMEM (3 * STAGE_BYTES)

template <int EPI>
__global__ __launch_bounds__(256, 2)
void tcgemm_kernel(const __half* __restrict__ A, const __half* __restrict__ B,
                   const float* __restrict__ bias, const float* __restrict__ R,
                   float* __restrict__ C, __half* __restrict__ Oa,
                   int M, int N, int K) {
    extern __shared__ __align__(1024) char smem[];
    uint32_t sbase = smem_to_u32(smem);
    const int tid = threadIdx.x;
    const int wid = tid >> 5, lid = tid & 31;
    const int wm = wid >> 2, wn = wid & 3;
    const int bm = blockIdx.y * 128, bn = blockIdx.x * 128;

    auto load_chunk = [&](int c, int s) {
        uint32_t tb = sbase + s * STAGE_BYTES;
        #pragma unroll
        for (int t2 = 0; t2 < 2; t2++) {
            const __half* src = t2 ? B : A;
            int rbase = t2 ? bn : bm;
            uint32_t dst0 = tb + t2 * 16384;
            #pragma unroll
            for (int i = 0; i < 4; i++) {
                int u = tid + i * 256;
                int r = u >> 3, j = u & 7;
                uint32_t d = dst0 + SWZ(r * 128 + j * 16);
                const void* g = src + (size_t)(rbase + r) * K + c * 64 + j * 8;
                asm volatile("cp.async.cg.shared.global [%0], [%1], 16;"
                             :: "r"(d), "l"(g) : "memory");
            }
        }
        asm volatile("cp.async.commit_group;" ::: "memory");
    };

    float acc[4][4][4];
    #pragma unroll
    for (int im = 0; im < 4; im++)
        #pragma unroll
        for (int in = 0; in < 4; in++)
            #pragma unroll
            for (int q = 0; q < 4; q++) acc[im][in][q] = 0.0f;

    const int nchunks = K >> 6;
    load_chunk(0, 0);
    load_chunk(1, 1);

    const int arow = wm * 64 + (lid & 15);
    const int acol = (lid >> 4) * 16;
    const int brow = wn * 32 + (lid & 7);
    const int bcol = ((lid >> 3) & 1) * 16;

    for (int c = 0; c < nchunks; c++) {
        if (c + 1 < nchunks) {
            asm volatile("cp.async.wait_group 1;" ::: "memory");
        } else {
            asm volatile("cp.async.wait_group 0;" ::: "memory");
        }
        __syncthreads();
        if (c + 2 < nchunks)
            load_chunk(c + 2, (c + 2) % 3);

        int s = c % 3;
        uint32_t tb = sbase + s * STAGE_BYTES;
        uint32_t tA = tb, tB = tb + 16384;

        #pragma unroll
        for (int ks = 0; ks < 4; ks++) {
            uint32_t a4[4][4], b2[4][2];
            #pragma unroll
            for (int im = 0; im < 4; im++) {
                uint32_t off = SWZ((arow + im * 16) * 128 + ks * 32 + acol);
                ldsm_x4(a4[im], tA + off);
            }
            #pragma unroll
            for (int in = 0; in < 4; in++) {
                uint32_t off = SWZ((brow + in * 8) * 128 + ks * 32 + bcol);
                ldsm_x2(b2[in], tB + off);
            }
            #pragma unroll
            for (int im = 0; im < 4; im++)
                #pragma unroll
                for (int in = 0; in < 4; in++)
                    mma_f16_g(acc[im][in], a4[im], b2[in]);
        }
    }

    #pragma unroll
    for (int im = 0; im < 4; im++) {
        #pragma unroll
        for (int in = 0; in < 4; in++) {
            int m0 = bm + wm * 64 + im * 16 + (lid >> 2);
            int n0 = bn + wn * 32 + in * 8 + (lid & 3) * 2;
            float b0 = bias[n0], b1 = bias[n0 + 1];
            #pragma unroll
            for (int half = 0; half < 2; half++) {
                int m = m0 + half * 8;
                float v0 = acc[im][in][half * 2]     + b0;
                float v1 = acc[im][in][half * 2 + 1] + b1;
                size_t off = (size_t)m * N + n0;
                if (EPI == EPI_HBIAS) {
                    *reinterpret_cast<__half2*>(&Oa[off]) = __floats2half2_rn(v0, v1);
                } else if (EPI == EPI_GELU) {
                    float g0 = 0.5f * v0 * (1.0f + erff(v0 * 0.70710678118654752f));
                    float g1 = 0.5f * v1 * (1.0f + erff(v1 * 0.70710678118654752f));
                    *reinterpret_cast<__half2*>(&Oa[off]) = __floats2half2_rn(g0, g1);
                } else {
                    float2 rr = *reinterpret_cast<const float2*>(&R[off]);
                    v0 += rr.x; v1 += rr.y;
                    float2 o2 = make_float2(v0, v1);
                    *reinterpret_cast<float2*>(&C[off]) = o2;
                }
            }
        }
    }
}

// ---------------------------------------------------------------------------
// fp16 flash attention, 128-row K/V loads, 64-wide S sub-chunks, 2 CTAs/SM.
// qkv contiguous [t, 3d] fp16. smem: Q 16K | 2 slots x {K 16K, V 16K} = 80K.
// Q fragments hoisted (loaded once). Heavy-first scheduling.
// ---------------------------------------------------------------------------
#define ATTN_SMEM (16384 + 2 * 32768)

__global__ __launch_bounds__(256, 2)
void attn_mma_kernel(const __half* __restrict__ qkv, __half* __restrict__ oa) {
    extern __shared__ __align__(1024) char smem_raw[];
    uint32_t sb = smem_to_u32(smem_raw);
    const uint32_t sQ = 0;

    const int tid = threadIdx.x;
    const int wid = tid >> 5, lid = tid & 31;
    const int qb = gridDim.x - 1 - blockIdx.x;   // heavy CTAs first
    const int h = blockIdx.y, b = blockIdx.z;
    const int qbase = qb * 128;
    const size_t tok0 = (size_t)b * TSEQ;

    auto load_kv = [&](int c, int s) {
        uint32_t slot = sb + 16384 + s * 32768;
        int rowbase = c * 128;
        #pragma unroll
        for (int i = 0; i < 8; i++) {
            int u = tid + i * 256;
            int t2 = u >> 10;
            int c2 = u & 1023;
            int r = c2 >> 3, j = c2 & 7;
            uint32_t d = slot + t2 * 16384 + SWZ(r * 128 + j * 16);
            const void* g = qkv + (tok0 + rowbase + r) * D3 + (t2 + 1) * D + h * HD + j * 8;
            asm volatile("cp.async.cg.shared.global [%0], [%1], 16;"
                         :: "r"(d), "l"(g) : "memory");
        }
    };

    {
        #pragma unroll
        for (int i = 0; i < 4; i++) {
            int u = tid + i * 256;
            int r = u >> 3, j = u & 7;
            uint32_t o = SWZ(r * 128 + j * 16);
            const void* g = qkv + (tok0 + qbase + r) * D3 + h * HD + j * 8;
            asm volatile("cp.async.cg.shared.global [%0], [%1], 16;"
                         :: "r"(sb + sQ + o), "l"(g) : "memory");
        }
        load_kv(0, 0);
        asm volatile("cp.async.commit_group;" ::: "memory");
    }

    float mrow[2] = {-1e30f, -1e30f};
    float lrow[2] = {0.0f, 0.0f};
    float oacc[8][4];
    #pragma unroll
    for (int t = 0; t < 8; t++)
        #pragma unroll
        for (int c = 0; c < 4; c++) oacc[t][c] = 0.0f;

    uint32_t qf[4][4];   // hoisted Q fragments (persist across chunks)

    const int nchunks = qb + 1;
    const int wrow_hi = qbase + 16 * wid + 15;
    const int kr = lid & 7;
    const int kcb = ((lid >> 3) & 1) * 16;
    const int vr = (lid & 7) + ((lid >> 3) & 1) * 8;

    for (int kc = 0; kc < nchunks; kc++) {
        const int s = kc & 1;
        if (kc + 1 < nchunks) {
            load_kv(kc + 1, s ^ 1);
            asm volatile("cp.async.commit_group;" ::: "memory");
            asm volatile("cp.async.wait_group 1;" ::: "memory");
        } else {
            asm volatile("cp.async.wait_group 0;" ::: "memory");
        }
        __syncthreads();

        if (kc == 0) {
            int qr = 16 * wid + (lid & 15);
            int qc = (lid >> 4) * 16;
            #pragma unroll
            for (int ks = 0; ks < 4; ks++) {
                uint32_t off = SWZ(qr * 128 + ks * 32 + qc);
                ldsm_x4(qf[ks], sb + sQ + off);
            }
        }

        const uint32_t slot = sb + 16384 + s * 32768;
        const uint32_t tK = slot, tV = slot + 16384;

        #pragma unroll
        for (int sub = 0; sub < 2; sub++) {
            const int kbase2 = kc * 128 + sub * 64;
            if (wrow_hi < kbase2) continue;   // warp-uniform skip above diagonal

            float sacc[8][4];
            #pragma unroll
            for (int t = 0; t < 8; t++)
                #pragma unroll
                for (int c = 0; c < 4; c++) sacc[t][c] = 0.0f;

            #pragma unroll
            for (int t = 0; t < 8; t++) {
                #pragma unroll
                for (int ks = 0; ks < 4; ks++) {
                    uint32_t off = SWZ((sub * 64 + t * 8 + kr) * 128 + ks * 32 + kcb);
                    uint32_t kf[2];
                    ldsm_x2(kf, tK + off);
                    mma_f16_g(sacc[t], qf[ks], kf);
                }
            }

            if (kc == qb) {   // diagonal block: mask
                int row0 = qbase + 16 * wid + (lid >> 2);
                #pragma unroll
                for (int t = 0; t < 8; t++) {
                    int col = kbase2 + t * 8 + 2 * (lid & 3);
                    if (col > row0)     sacc[t][0] = -1e30f;
                    if (col + 1 > row0) sacc[t][1] = -1e30f;
                    if (col > row0 + 8)     sacc[t][2] = -1e30f;
                    if (col + 1 > row0 + 8) sacc[t][3] = -1e30f;
                }
            }

            #pragma unroll
            for (int rr = 0; rr < 2; rr++) {
                float mx = -1e30f;
                #pragma unroll
                for (int t = 0; t < 8; t++)
                    mx = fmaxf(mx, fmaxf(sacc[t][2 * rr], sacc[t][2 * rr + 1]));
                mx = fmaxf(mx, __shfl_xor_sync(0xffffffffu, mx, 1));
                mx = fmaxf(mx, __shfl_xor_sync(0xffffffffu, mx, 2));
                float mn = fmaxf(mrow[rr], mx);
                float sc = __expf(mrow[rr] - mn);
                mrow[rr] = mn;
                float rs = 0.0f;
                #pragma unroll
                for (int t = 0; t < 8; t++) {
                    float p0 = __expf(sacc[t][2 * rr] - mn);
                    float p1 = __expf(sacc[t][2 * rr + 1] - mn);
                    sacc[t][2 * rr] = p0; sacc[t][2 * rr + 1] = p1;
                    rs += p0 + p1;
                }
                lrow[rr] = lrow[rr] * sc + rs;
                #pragma unroll
                for (int t = 0; t < 8; t++) {
                    oacc[t][2 * rr]     *= sc;
                    oacc[t][2 * rr + 1] *= sc;
                }
            }

            #pragma unroll
            for (int j = 0; j < 4; j++) {
                uint32_t pf[4];
                #pragma unroll
                for (int half = 0; half < 2; half++) {
                    float a0 = sacc[2 * j + half][0], a1 = sacc[2 * j + half][1];
                    float a2 = sacc[2 * j + half][2], a3 = sacc[2 * j + half][3];
                    pf[0 + 2 * half] = pack_f16x2(a0, a1);
                    pf[1 + 2 * half] = pack_f16x2(a2, a3);
                }
                #pragma unroll
                for (int t = 0; t < 8; t++) {
                    uint32_t voff = SWZ((sub * 64 + j * 16 + vr) * 128 + t * 16);
                    uint32_t vf[2];
                    ldsm_x2_trans(vf, tV + voff);
                    mma_f16_g(oacc[t], pf, vf);
                }
            }
        }
        __syncthreads();
    }

    lrow[0] += __shfl_xor_sync(0xffffffffu, lrow[0], 1);
    lrow[0] += __shfl_xor_sync(0xffffffffu, lrow[0], 2);
    lrow[1] += __shfl_xor_sync(0xffffffffu, lrow[1], 1);
    lrow[1] += __shfl_xor_sync(0xffffffffu, lrow[1], 2);
    float inv0 = 0.03125f / lrow[0];
    float inv1 = 0.03125f / lrow[1];

    #pragma unroll
    for (int rr = 0; rr < 2; rr++) {
        float inv = rr ? inv1 : inv0;
        int row = qbase + 16 * wid + (lid >> 2) + rr * 8;
        size_t base = (tok0 + row) * (size_t)D + h * HD + 2 * (lid & 3);
        #pragma unroll
        for (int t = 0; t < 8; t++) {
            float v0 = oacc[t][2 * rr] * inv;
            float v1 = oacc[t][2 * rr + 1] * inv;
            *reinterpret_cast<__half2*>(&oa[base + t * 8]) = __floats2half2_rn(v0, v1);
        }
    }
}

// ---------------------------------------------------------------------------
// Launch (fork weight transposes onto a side stream; join before proj)
// ---------------------------------------------------------------------------
extern "C" void kernel_launch(void* const* d_in, const int* in_sizes, int n_in,
                              void* d_out, int out_size) {
    const float* x      = (const float*)d_in[0];
    const float* w_attn = (const float*)d_in[1];
    const float* b_attn = (const float*)d_in[2];
    const float* w_proj = (const float*)d_in[3];
    const float* b_proj = (const float*)d_in[4];
    const float* w_fc1  = (const float*)d_in[5];
    const float* b_fc1  = (const float*)d_in[6];
    const float* w_fc2  = (const float*)d_in[7];
    const float* b_fc2  = (const float*)d_in[8];
    const float* g1     = (const float*)d_in[9];
    const float* g2     = (const float*)d_in[10];
    float* out = (float*)d_out;

    __half *a, *act, *qkv, *tA, *tP, *tF1, *tF2;
    cudaGetSymbolAddress((void**)&a,   g_a);
    cudaGetSymbolAddress((void**)&act, g_act);
    cudaGetSymbolAddress((void**)&qkv, g_qkv);
    cudaGetSymbolAddress((void**)&tA,  g_wA);
    cudaGetSymbolAddress((void**)&tP,  g_wP);
    cudaGetSymbolAddress((void**)&tF1, g_wF1);
    cudaGetSymbolAddress((void**)&tF2, g_wF2);

    cudaFuncSetAttribute(attn_mma_kernel, cudaFuncAttributeMaxDynamicSharedMemorySize, ATTN_SMEM);
    cudaFuncSetAttribute(tcgemm_kernel<EPI_HBIAS>, cudaFuncAttributeMaxDynamicSharedMemorySize, TCG_SMEM);
    cudaFuncSetAttribute(tcgemm_kernel<EPI_GELU>,  cudaFuncAttributeMaxDynamicSharedMemorySize, TCG_SMEM);
    cudaFuncSetAttribute(tcgemm_kernel<EPI_RES>,   cudaFuncAttributeMaxDynamicSharedMemorySize, TCG_SMEM);

    // side stream for late-use weight transposes (kernel_launch runs only for
    // the correctness call and the single capture call, so per-call creation
    // cost is irrelevant; not destroyed to keep capture valid)
    cudaStream_t s2;
    cudaStreamCreateWithFlags(&s2, cudaStreamNonBlocking);
    cudaEvent_t evF, evJ;
    cudaEventCreateWithFlags(&evF, cudaEventDisableTiming);
    cudaEventCreateWithFlags(&evJ, cudaEventDisableTiming);

    cudaEventRecord(evF, 0);
    cudaStreamWaitEvent(s2, evF, 0);
    prep_w_kernel<<<9216, 256, 0, s2>>>(w_proj, w_fc1, w_fc2, tP, tF1, tF2);
    cudaEventRecord(evJ, s2);

    // main stream: rmsnorm1 + wA transpose
    prep_main_kernel<<<NTOK + 3072, 256>>>(x, g1, a, w_attn, tA);
    // qkv = h @ w_attn + b_attn -> contiguous fp16 [t, 3d]
    tcgemm_kernel<EPI_HBIAS><<<dim3(D3 / 128, NTOK / 128), 256, TCG_SMEM>>>(
        a, tA, b_attn, nullptr, nullptr, qkv, NTOK, D3, D);
    // attention -> fp16 into a
    attn_mma_kernel<<<dim3(TSEQ / 128, NH, NBATCH), 256, ATTN_SMEM>>>(qkv, a);
    // join side stream before proj (needs tP; fc1/fc2 follow on main stream)
    cudaStreamWaitEvent(0, evJ, 0);
    // out = x + o @ w_proj + b_proj
    tcgemm_kernel<EPI_RES><<<dim3(D / 128, NTOK / 128), 256, TCG_SMEM>>>(
        a, tP, b_proj, x, out, nullptr, NTOK, D, D);
    // rmsnorm2 -> fp16
    rmsnorm_h_kernel<<<NTOK, 256>>>(out, g2, a);
    // act = gelu(h @ w_fc1 + b_fc1) -> fp16
    tcgemm_kernel<EPI_GELU><<<dim3(D4 / 128, NTOK / 128), 256, TCG_SMEM>>>(
        a, tF1, b_fc1, nullptr, nullptr, act, NTOK, D4, D);
    // out = out + act @ w_fc2 + b_fc2
    tcgemm_kernel<EPI_RES><<<dim3(D / 128, NTOK / 128), 256, TCG_SMEM>>>(
        act, tF2, b_fc2, out, out, nullptr, NTOK, D, D4);
}